// round 13
// baseline (speedup 1.0000x reference)
#include <cuda_runtime.h>
#include <cuda_fp16.h>

#define HEADS 8
#define DIM_HEAD 64
#define BATCH 4
#define SEQ 2048
#define DMODEL 512
#define M_ROWS (BATCH * SEQ)           // 8192
#define QK_SCALE 0.125f                // 64^-0.5
#define FULLMASK 0xffffffffu
#define PERM(c) ((((c) & 7) << 3) | ((c) >> 3))   // 64-wide word perm (tf32 GEMM path)
#define P32(w)  ((((w) & 7) << 2) | ((w) >> 3))   // 32-wide half2-word perm (fp16 attn)

// Scratch (device-global; no allocation allowed)
// g_a:  [m][(k&~63)+PERM(k&63)] query, tf32-rounded (fp32)
// g_wt: [z][n][(k&~63)+PERM(k&63)] transposed weights, tf32-rounded (fp32)
// g_q:  half [b,h,n][P32 half2-word perm of d]  (pre-scaled by QK_SCALE)
// g_k:  half [b,h,n][P32 half2-word perm of d]
// g_v:  half [b,h,d][(key&~63) + P32((key&63)/2)*2 + (key&1)]  (transposed)
// g_o:  fp32 [b,n][(c&~63)+PERM(c&63)] attn out, tf32-rounded
__device__ float  g_a[M_ROWS * DMODEL];
__device__ float  g_wt[4 * DMODEL * DMODEL];
__device__ __half g_q[BATCH * HEADS * SEQ * DIM_HEAD];
__device__ __half g_k[BATCH * HEADS * SEQ * DIM_HEAD];
__device__ __half g_v[BATCH * HEADS * SEQ * DIM_HEAD];
__device__ float  g_o[BATCH * SEQ * DMODEL];

__device__ __forceinline__ unsigned f2tf(float x) {
    unsigned u;
    asm("cvt.rna.tf32.f32 %0, %1;" : "=r"(u) : "f"(x));
    return u;
}
__device__ __forceinline__ float roundtf(float x) { return __uint_as_float(f2tf(x)); }

__device__ __forceinline__ void mma_tf32(float* c, const unsigned* a, const unsigned* b) {
    asm volatile(
        "mma.sync.aligned.m16n8k8.row.col.f32.tf32.tf32.f32 "
        "{%0,%1,%2,%3}, {%4,%5,%6,%7}, {%8,%9}, {%0,%1,%2,%3};"
        : "+f"(c[0]), "+f"(c[1]), "+f"(c[2]), "+f"(c[3])
        : "r"(a[0]), "r"(a[1]), "r"(a[2]), "r"(a[3]), "r"(b[0]), "r"(b[1]));
}

__device__ __forceinline__ void mma_f16(float* c, const unsigned* a, unsigned b0, unsigned b1) {
    asm volatile(
        "mma.sync.aligned.m16n8k16.row.col.f32.f16.f16.f32 "
        "{%0,%1,%2,%3}, {%4,%5,%6,%7}, {%8,%9}, {%0,%1,%2,%3};"
        : "+f"(c[0]), "+f"(c[1]), "+f"(c[2]), "+f"(c[3])
        : "r"(a[0]), "r"(a[1]), "r"(a[2]), "r"(a[3]), "r"(b0), "r"(b1));
}

__device__ __forceinline__ unsigned packh2(float lo, float hi) {
    __half2 h = __floats2half2_rn(lo, hi);
    return *(unsigned*)&h;
}

// tf32 GEMM fragment helper (unchanged)
struct Frag8 { unsigned a[8]; unsigned b[8]; };
__device__ __forceinline__ void load_frag8(const unsigned* base, int t, Frag8& f) {
    const uint4* p = (const uint4*)base;
    uint4 x0 = p[t * 2], x1 = p[t * 2 + 1];
    uint4 y0 = p[(t + 4) * 2], y1 = p[(t + 4) * 2 + 1];
    f.a[0] = x0.x; f.a[1] = x0.y; f.a[2] = x0.z; f.a[3] = x0.w;
    f.a[4] = x1.x; f.a[5] = x1.y; f.a[6] = x1.z; f.a[7] = x1.w;
    f.b[0] = y0.x; f.b[1] = y0.y; f.b[2] = y0.z; f.b[3] = y0.w;
    f.b[4] = y1.x; f.b[5] = y1.y; f.b[6] = y1.z; f.b[7] = y1.w;
}

// ---------------------------------------------------------------------------
// prep_a / prep_w : unchanged tf32 paths
// ---------------------------------------------------------------------------
__global__ __launch_bounds__(256)
void prep_a(const float* __restrict__ query)
{
    int idx = blockIdx.x * 256 + threadIdx.x;
    int m = idx >> 7, c4 = idx & 127;
    int k = c4 * 4;
    float4 v = *(const float4*)(query + (size_t)m * DMODEL + k);
    float* dst = g_a + (size_t)m * DMODEL + (k & ~63);
    dst[PERM((k + 0) & 63)] = roundtf(v.x);
    dst[PERM((k + 1) & 63)] = roundtf(v.y);
    dst[PERM((k + 2) & 63)] = roundtf(v.z);
    dst[PERM((k + 3) & 63)] = roundtf(v.w);
}

__global__ __launch_bounds__(256)
void prep_w(const float* __restrict__ W0, const float* __restrict__ W1,
            const float* __restrict__ W2, const float* __restrict__ W3)
{
    __shared__ float sm[64][68];
    const int z = blockIdx.z;
    const float* __restrict__ W = (z == 0) ? W0 : (z == 1) ? W1 : (z == 2) ? W2 : W3;
    const int n0 = blockIdx.x * 64;
    const int k0 = blockIdx.y * 64;
    const int tid = threadIdx.x;

#pragma unroll
    for (int i = 0; i < 4; i++) {
        int f4 = tid + i * 256;
        int kr = f4 >> 4, nq = f4 & 15;
        float4 v = *(const float4*)(W + (size_t)(k0 + kr) * DMODEL + n0 + nq * 4);
        sm[nq * 4 + 0][PERM(kr)] = roundtf(v.x);
        sm[nq * 4 + 1][PERM(kr)] = roundtf(v.y);
        sm[nq * 4 + 2][PERM(kr)] = roundtf(v.z);
        sm[nq * 4 + 3][PERM(kr)] = roundtf(v.w);
    }
    __syncthreads();
    float* dstz = g_wt + (size_t)z * DMODEL * DMODEL;
#pragma unroll
    for (int i = 0; i < 4; i++) {
        int f4 = tid + i * 256;
        int nr = f4 >> 4, q = f4 & 15;
        *(float4*)(dstz + (size_t)(n0 + nr) * DMODEL + k0 + q * 4) =
            *(const float4*)&sm[nr][q * 4];
    }
}

// ---------------------------------------------------------------------------
// tf32 GEMM (unchanged mainloop); epilogue now writes fp16 attn layouts.
// ---------------------------------------------------------------------------
#define GA_WORDS (128 * 68)
#define GB_WORDS (64 * 68)

template <bool OUT>
__global__ __launch_bounds__(256)
void gemm_fast(float* __restrict__ Cext)
{
    extern __shared__ unsigned gsm[];
    unsigned* Asm = gsm;
    unsigned* Bsm = gsm + 2 * GA_WORDS;

    const int z = OUT ? 3 : blockIdx.z;
    const float* __restrict__ A = OUT ? g_o : g_a;
    const float* __restrict__ B = g_wt + (size_t)z * DMODEL * DMODEL;

    const int tid  = threadIdx.x;
    const int warp = tid >> 5, lane = tid & 31;
    const int g = lane >> 2, t = lane & 3;
    const int wm = warp & 3, wn = warp >> 2;
    const int m0 = blockIdx.y * 128;
    const int c0 = blockIdx.x * 64;

    const unsigned as_base = (unsigned)__cvta_generic_to_shared(Asm);
    const unsigned bs_base = (unsigned)__cvta_generic_to_shared(Bsm);

    float acc[2][4][4];
#pragma unroll
    for (int i = 0; i < 2; i++)
#pragma unroll
        for (int j = 0; j < 4; j++)
#pragma unroll
            for (int k = 0; k < 4; k++) acc[i][j][k] = 0.f;

#define G_ISSUE(k0, buf)                                                              \
    {                                                                                 \
        _Pragma("unroll")                                                             \
        for (int i = 0; i < 8; i++) {                                                 \
            int f4  = tid + i * 256;                                                  \
            int row = f4 >> 4, q = f4 & 15;                                           \
            const float* src = A + (size_t)(m0 + row) * DMODEL + (k0) + q * 4;        \
            unsigned dst = as_base + ((buf) * GA_WORDS + row * 68 + q * 4) * 4;       \
            asm volatile("cp.async.cg.shared.global [%0], [%1], 16;\n"                \
                         :: "r"(dst), "l"(src));                                      \
        }                                                                             \
        _Pragma("unroll")                                                             \
        for (int i = 0; i < 4; i++) {                                                 \
            int f4  = tid + i * 256;                                                  \
            int row = f4 >> 4, q = f4 & 15;                                           \
            const float* src = B + (size_t)(c0 + row) * DMODEL + (k0) + q * 4;        \
            unsigned dst = bs_base + ((buf) * GB_WORDS + row * 68 + q * 4) * 4;       \
            asm volatile("cp.async.cg.shared.global [%0], [%1], 16;\n"                \
                         :: "r"(dst), "l"(src));                                      \
        }                                                                             \
        asm volatile("cp.async.commit_group;\n");                                     \
    }

    G_ISSUE(0, 0);

    for (int c = 0; c < DMODEL / 64; c++) {
        const int buf = c & 1;
        if (c + 1 < DMODEL / 64) {
            __syncthreads();
            G_ISSUE((c + 1) * 64, buf ^ 1);
            asm volatile("cp.async.wait_group 1;\n");
        } else {
            asm volatile("cp.async.wait_group 0;\n");
        }
        __syncthreads();

        const unsigned* Asb = Asm + buf * GA_WORDS;
        const unsigned* Bsb = Bsm + buf * GB_WORDS;

        Frag8 fa[4];
        load_frag8(Asb + (wm * 32 + g) * 68,      t, fa[0]);
        load_frag8(Asb + (wm * 32 + 8 + g) * 68,  t, fa[1]);
        load_frag8(Asb + (wm * 32 + 16 + g) * 68, t, fa[2]);
        load_frag8(Asb + (wm * 32 + 24 + g) * 68, t, fa[3]);

#pragma unroll
        for (int nt = 0; nt < 4; nt++) {
            Frag8 fb;
            load_frag8(Bsb + (wn * 32 + nt * 8 + g) * 68, t, fb);
#pragma unroll
            for (int ks = 0; ks < 8; ks++) {
                unsigned bfr[2] = {fb.a[ks], fb.b[ks]};
                unsigned af0[4] = {fa[0].a[ks], fa[1].a[ks], fa[0].b[ks], fa[1].b[ks]};
                mma_tf32(acc[0][nt], af0, bfr);
                unsigned af1[4] = {fa[2].a[ks], fa[3].a[ks], fa[2].b[ks], fa[3].b[ks]};
                mma_tf32(acc[1][nt], af1, bfr);
            }
        }
    }
#undef G_ISSUE

#pragma unroll
    for (int mt = 0; mt < 2; mt++) {
#pragma unroll
        for (int nt = 0; nt < 4; nt++) {
#pragma unroll
            for (int half = 0; half < 2; half++) {
                int m = m0 + wm * 32 + mt * 16 + g + half * 8;
                int c = c0 + wn * 32 + nt * 8 + 2 * t;
                float v0 = acc[mt][nt][half * 2 + 0];
                float v1 = acc[mt][nt][half * 2 + 1];
                if (OUT) {
                    *(float2*)&Cext[(size_t)m * DMODEL + c] = make_float2(v0, v1);
                } else {
                    int b = m >> 11, n = m & 2047;
                    int hh = c >> 6, d = c & 63;   // d even
                    size_t bh = (size_t)b * HEADS + hh;
                    if (z == 0) {
                        int p = P32(d >> 1);
                        ((__half2*)(g_q + (bh * SEQ + n) * DIM_HEAD))[p] =
                            __floats2half2_rn(v0 * QK_SCALE, v1 * QK_SCALE);
                    } else if (z == 1) {
                        int p = P32(d >> 1);
                        ((__half2*)(g_k + (bh * SEQ + n) * DIM_HEAD))[p] =
                            __floats2half2_rn(v0, v1);
                    } else {
                        int w = (n & 63) >> 1;
                        size_t col = (size_t)(n & ~63) + P32(w) * 2 + (n & 1);
                        g_v[(bh * DIM_HEAD + d) * SEQ + col]     = __float2half(v0);
                        g_v[(bh * DIM_HEAD + d + 1) * SEQ + col] = __float2half(v1);
                    }
                }
            }
        }
    }
}

// ---------------------------------------------------------------------------
// Flash attention, fp16 m16n8k16. Block = 128 query rows (8 warps x 16),
// key chunks of 64. K/V half tiles staged via cp.async, double-buffered.
// Smem row stride 48 words (192B) -> conflict-free LDS.128 fragment loads.
// No P-relayout shuffles: m16n8k16 A-frag == two stacked m16n8k8 C-frags.
// dynamic smem: 4 tiles x 64 x 48 words = 49152 B
// ---------------------------------------------------------------------------
#define KROW_W 48
#define TILE_WORDS (64 * KROW_W)

__global__ __launch_bounds__(256, 2)
void attn_f16(const float* __restrict__ bias)
{
    extern __shared__ unsigned smem_u[];
    unsigned* Ksm = smem_u;                    // [2][64][48]
    unsigned* Vsm = smem_u + 2 * TILE_WORDS;   // [2][64][48]

    const int tid  = threadIdx.x;
    const int warp = tid >> 5, lane = tid & 31;
    const int g = lane >> 2, t = lane & 3;
    const int bh = blockIdx.y;
    const int h  = bh & (HEADS - 1);
    const int b  = bh >> 3;
    const int qw = blockIdx.x * 128 + warp * 16;

    const __half* __restrict__ Qg = g_q + (size_t)bh * SEQ * DIM_HEAD;
    const __half* __restrict__ Kg = g_k + (size_t)bh * SEQ * DIM_HEAD;
    const __half* __restrict__ Vg = g_v + (size_t)bh * DIM_HEAD * SEQ;
    const float*  __restrict__ bp0 = bias + ((size_t)h * SEQ + qw + g) * SEQ;
    const float*  __restrict__ bp1 = bias + ((size_t)h * SEQ + qw + g + 8) * SEQ;

    const unsigned ks_base = (unsigned)__cvta_generic_to_shared(Ksm);
    const unsigned vs_base = (unsigned)__cvta_generic_to_shared(Vsm);

    // Q A-frags: per kstep {rowg@w, rowg8@w, rowg@w+4, rowg8@w+4}, w = ks*8+t
    unsigned qa[4][4];
    {
        const uint4* Qr0 = (const uint4*)(Qg + (size_t)(qw + g) * DIM_HEAD);
        const uint4* Qr1 = (const uint4*)(Qg + (size_t)(qw + g + 8) * DIM_HEAD);
        uint4 qx0 = Qr0[t], qy0 = Qr0[t + 4];
        uint4 qx1 = Qr1[t], qy1 = Qr1[t + 4];
        const unsigned* px0 = (const unsigned*)&qx0;
        const unsigned* py0 = (const unsigned*)&qy0;
        const unsigned* px1 = (const unsigned*)&qx1;
        const unsigned* py1 = (const unsigned*)&qy1;
#pragma unroll
        for (int ks = 0; ks < 4; ks++) {
            qa[ks][0] = px0[ks]; qa[ks][1] = px1[ks];
            qa[ks][2] = py0[ks]; qa[ks][3] = py1[ks];
        }
    }

    float o[8][4];
#pragma unroll
    for (int i = 0; i < 8; i++)
#pragma unroll
        for (int j = 0; j < 4; j++) o[i][j] = 0.f;

    float m0r = -1e30f, m1r = -1e30f, l0 = 0.f, l1 = 0.f;

    // staging: K tile 64 rows x 8 chunks(16B) = 512; V same; 4 chunks/thread
#define ISSUE_CHUNK(kt, buf)                                                          \
    {                                                                                 \
        _Pragma("unroll")                                                             \
        for (int i = 0; i < 2; i++) {                                                 \
            int cidx = tid + i * 256;                                                 \
            int row = cidx >> 3, q = cidx & 7;                                        \
            unsigned off = ((buf) * TILE_WORDS + row * KROW_W + q * 4) * 4;           \
            const __half* ksrc = Kg + (size_t)((kt) + row) * DIM_HEAD + q * 8;        \
            asm volatile("cp.async.cg.shared.global [%0], [%1], 16;\n"                \
                         :: "r"(ks_base + off), "l"(ksrc));                           \
            const __half* vsrc = Vg + (size_t)row * SEQ + (kt) + q * 8;               \
            asm volatile("cp.async.cg.shared.global [%0], [%1], 16;\n"                \
                         :: "r"(vs_base + off), "l"(vsrc));                           \
        }                                                                             \
        asm volatile("cp.async.commit_group;\n");                                     \
    }

    ISSUE_CHUNK(0, 0);

    for (int c = 0; c < SEQ / 64; c++) {
        const int buf = c & 1;
        const int kt = c * 64;
        if (c + 1 < SEQ / 64) {
            __syncthreads();
            ISSUE_CHUNK(kt + 64, buf ^ 1);
            asm volatile("cp.async.wait_group 1;\n");
        } else {
            asm volatile("cp.async.wait_group 0;\n");
        }
        __syncthreads();

        const unsigned* Ks = Ksm + buf * TILE_WORDS;
        const unsigned* Vt = Vsm + buf * TILE_WORDS;

        // S = Q K^T : 8 key-groups of 8, 4 k-steps of 16
        float s[8][4];
#pragma unroll
        for (int i = 0; i < 8; i++)
#pragma unroll
            for (int j = 0; j < 4; j++) s[i][j] = 0.f;

#pragma unroll
        for (int p = 0; p < 4; p++) {
            const unsigned* r0 = Ks + ((2 * p) * 8 + g) * KROW_W;
            const unsigned* r1 = Ks + ((2 * p + 1) * 8 + g) * KROW_W;
            uint4 x0 = *(const uint4*)(r0 + t * 4), y0 = *(const uint4*)(r0 + (t + 4) * 4);
            uint4 x1 = *(const uint4*)(r1 + t * 4), y1 = *(const uint4*)(r1 + (t + 4) * 4);
            const unsigned* ax0 = (const unsigned*)&x0;
            const unsigned* ay0 = (const unsigned*)&y0;
            const unsigned* ax1 = (const unsigned*)&x1;
            const unsigned* ay1 = (const unsigned*)&y1;
#pragma unroll
            for (int ks = 0; ks < 4; ks++) {
                mma_f16(s[2 * p],     qa[ks], ax0[ks], ay0[ks]);
                mma_f16(s[2 * p + 1], qa[ks], ax1[ks], ay1[ks]);
            }
        }

        // bias + running max
        float mx0 = m0r, mx1 = m1r;
#pragma unroll
        for (int nt = 0; nt < 8; nt++) {
            float2 bb0 = *(const float2*)(bp0 + kt + nt * 8 + 2 * t);
            float2 bb1 = *(const float2*)(bp1 + kt + nt * 8 + 2 * t);
            s[nt][0] += bb0.x; s[nt][1] += bb0.y;
            s[nt][2] += bb1.x; s[nt][3] += bb1.y;
            mx0 = fmaxf(mx0, fmaxf(s[nt][0], s[nt][1]));
            mx1 = fmaxf(mx1, fmaxf(s[nt][2], s[nt][3]));
        }
        mx0 = fmaxf(mx0, __shfl_xor_sync(FULLMASK, mx0, 1));
        mx0 = fmaxf(mx0, __shfl_xor_sync(FULLMASK, mx0, 2));
        mx1 = fmaxf(mx1, __shfl_xor_sync(FULLMASK, mx1, 1));
        mx1 = fmaxf(mx1, __shfl_xor_sync(FULLMASK, mx1, 2));

        const float cr0 = __expf(m0r - mx0);
        const float cr1 = __expf(m1r - mx1);
        m0r = mx0; m1r = mx1;

        float ls0 = 0.f, ls1 = 0.f;
#pragma unroll
        for (int nt = 0; nt < 8; nt++) {
            s[nt][0] = __expf(s[nt][0] - mx0);
            s[nt][1] = __expf(s[nt][1] - mx0);
            s[nt][2] = __expf(s[nt][2] - mx1);
            s[nt][3] = __expf(s[nt][3] - mx1);
            ls0 += s[nt][0] + s[nt][1];
            ls1 += s[nt][2] + s[nt][3];
            o[nt][0] *= cr0; o[nt][1] *= cr0;
            o[nt][2] *= cr1; o[nt][3] *= cr1;
        }
        ls0 += __shfl_xor_sync(FULLMASK, ls0, 1);
        ls0 += __shfl_xor_sync(FULLMASK, ls0, 2);
        ls1 += __shfl_xor_sync(FULLMASK, ls1, 1);
        ls1 += __shfl_xor_sync(FULLMASK, ls1, 2);
        l0 = l0 * cr0 + ls0;
        l1 = l1 * cr1 + ls1;

        // P -> fp16 A-frags: NO shuffles (A-frag == two stacked C-frags)
        unsigned pa[4][4];
#pragma unroll
        for (int j = 0; j < 4; j++) {
            pa[j][0] = packh2(s[2 * j][0],     s[2 * j][1]);
            pa[j][1] = packh2(s[2 * j][2],     s[2 * j][3]);
            pa[j][2] = packh2(s[2 * j + 1][0], s[2 * j + 1][1]);
            pa[j][3] = packh2(s[2 * j + 1][2], s[2 * j + 1][3]);
        }

        // O += P @ V : 8 dh-groups of 8, 4 key-steps of 16
#pragma unroll
        for (int p = 0; p < 4; p++) {
            const unsigned* r0 = Vt + ((2 * p) * 8 + g) * KROW_W;
            const unsigned* r1 = Vt + ((2 * p + 1) * 8 + g) * KROW_W;
            uint4 x0 = *(const uint4*)(r0 + t * 4), y0 = *(const uint4*)(r0 + (t + 4) * 4);
            uint4 x1 = *(const uint4*)(r1 + t * 4), y1 = *(const uint4*)(r1 + (t + 4) * 4);
            const unsigned* ax0 = (const unsigned*)&x0;
            const unsigned* ay0 = (const unsigned*)&y0;
            const unsigned* ax1 = (const unsigned*)&x1;
            const unsigned* ay1 = (const unsigned*)&y1;
#pragma unroll
            for (int j = 0; j < 4; j++) {
                mma_f16(o[2 * p],     pa[j], ax0[j], ay0[j]);
                mma_f16(o[2 * p + 1], pa[j], ax1[j], ay1[j]);
            }
        }
    }

    // normalize + write g_o (tf32-rounded, PERM'd for gemm_fast<OUT> A-path)
    const float inv0 = 1.f / l0, inv1 = 1.f / l1;
    float* __restrict__ Og = g_o + ((size_t)b * SEQ + qw) * DMODEL + h * DIM_HEAD;
#pragma unroll
    for (int nt = 0; nt < 8; nt++) {
        int cc = nt * 8 + 2 * t;            // even
        int p = PERM(cc);                   // PERM(cc+1) == p + 8
        Og[(size_t)g * DMODEL + p]           = roundtf(o[nt][0] * inv0);
        Og[(size_t)g * DMODEL + p + 8]       = roundtf(o[nt][1] * inv0);
        Og[(size_t)(g + 8) * DMODEL + p]     = roundtf(o[nt][2] * inv1);
        Og[(size_t)(g + 8) * DMODEL + p + 8] = roundtf(o[nt][3] * inv1);
    }
}

// ---------------------------------------------------------------------------
extern "C" void kernel_launch(void* const* d_in, const int* in_sizes, int n_in,
                              void* d_out, int out_size)
{
    const float* query = (const float*)d_in[0];
    const float* bias  = (const float*)d_in[1];
    const float* Wq    = (const float*)d_in[2];
    const float* Wk    = (const float*)d_in[3];
    const float* Wv    = (const float*)d_in[4];
    const float* Wout  = (const float*)d_in[5];
    float* out = (float*)d_out;

    const int attn_smem = 4 * TILE_WORDS * 4;            // 49152 B
    const int gemm_smem = 2 * (GA_WORDS + GB_WORDS) * 4; // 104448 B
    cudaFuncSetAttribute(attn_f16, cudaFuncAttributeMaxDynamicSharedMemorySize,
                         attn_smem);
    cudaFuncSetAttribute(gemm_fast<false>, cudaFuncAttributeMaxDynamicSharedMemorySize,
                         gemm_smem);
    cudaFuncSetAttribute(gemm_fast<true>, cudaFuncAttributeMaxDynamicSharedMemorySize,
                         gemm_smem);

    prep_a<<<M_ROWS * (DMODEL / 4) / 256, 256>>>(query);
    prep_w<<<dim3(8, 8, 4), 256>>>(Wq, Wk, Wv, Wout);

    dim3 qkv_grid(DMODEL / 64, M_ROWS / 128, 3);   // (8, 64, 3)
    gemm_fast<false><<<qkv_grid, 256, gemm_smem>>>(nullptr);

    dim3 attn_grid(SEQ / 128, BATCH * HEADS);      // (16, 32)
    attn_f16<<<attn_grid, 256, attn_smem>>>(bias);

    dim3 out_grid(DMODEL / 64, M_ROWS / 128);      // (8, 64)
    gemm_fast<true><<<out_grid, 256, gemm_smem>>>(out);
}